// round 15
// baseline (speedup 1.0000x reference)
#include <cuda_runtime.h>
#include <cuda_bf16.h>

// Problem constants
#define BB 32
#define CC 64
#define TT 4096
#define NVEC ((BB * CC * TT) / 4)   // 2,097,152 float4 vectors
#define TVEC (TT / 4)               // 1024 (power of two)

#define GRID 1024
#define BLOCK 256
#define NWARPS (BLOCK / 32)
#define TOTAL_WARPS (GRID * NWARPS)     // 8192
#define ITERS (NVEC / (GRID * BLOCK))   // exactly 8

// Fixed-point scale for deterministic integer accumulation.
#define FXP 1048576.0               // 2^20

__device__ unsigned long long g_total = 0;   // fixed-point grand total
__device__ unsigned int g_done_warps = 0;    // self-resetting per launch

__device__ __forceinline__ float wabs4(const float4& p, const float4& t, float w)
{
    return fabsf(p.x - t.x) * w + fabsf(p.y - t.y) * (w - 1.0f)
         + fabsf(p.z - t.z) * (w - 2.0f) + fabsf(p.w - t.w) * (w - 3.0f);
}

// R7 champion memory loop + sync-free warp-granular tail:
// no __syncthreads, no smem — every warp reduces via shfl, contributes one
// deterministic u64 fixed-point atomicAdd, and retires independently.
__global__ __launch_bounds__(BLOCK, 8) void wass_fused_kernel(
    const float4* __restrict__ yp, const float4* __restrict__ yt,
    float* __restrict__ out)
{
    const int v0 = blockIdx.x * BLOCK + threadIdx.x;
    const int S  = GRID * BLOCK;

    float acc = 0.0f;

    #pragma unroll
    for (int c = 0; c < ITERS / 2; c++) {
        const int va = v0 + (2 * c + 0) * S;
        const int vb = v0 + (2 * c + 1) * S;

        // 4 loads front-batched before any compute.
        float4 p0 = yp[va];
        float4 t0 = yt[va];
        float4 p1 = yp[vb];
        float4 t1 = yt[vb];

        acc += wabs4(p0, t0, (float)(TT - 4 * (va & (TVEC - 1))));
        acc += wabs4(p1, t1, (float)(TT - 4 * (vb & (TVEC - 1))));
    }

    // Warp-level reduce (no smem, no bar.sync).
    #pragma unroll
    for (int off = 16; off > 0; off >>= 1)
        acc += __shfl_down_sync(0xFFFFFFFFu, acc, off);

    if ((threadIdx.x & 31) == 0) {
        // Deterministic contribution: fixed-point u64, commutative addition.
        unsigned long long q =
            (unsigned long long)__double2ll_rn((double)acc * FXP);
        atomicAdd(&g_total, q);
        __threadfence();                       // total add visible before counting
        unsigned int n = atomicAdd(&g_done_warps, 1u);
        if (n == TOTAL_WARPS - 1) {
            // Last warp of the launch: publish and reset for graph replay.
            unsigned long long tot = g_total;
            double scaling = 2.0 / ((double)TT * (double)CC * (double)(TT + 1));
            out[0] = (float)(((double)tot / FXP) * scaling / (double)BB);
            g_total = 0ULL;
            g_done_warps = 0;
        }
    }
}

extern "C" void kernel_launch(void* const* d_in, const int* in_sizes, int n_in,
                              void* d_out, int out_size)
{
    const float4* yp = reinterpret_cast<const float4*>(d_in[0]);
    const float4* yt = reinterpret_cast<const float4*>(d_in[1]);
    float* out = reinterpret_cast<float*>(d_out);
    wass_fused_kernel<<<GRID, BLOCK>>>(yp, yt, out);
}

// round 17
// speedup vs baseline: 1.4913x; 1.4913x over previous
#include <cuda_runtime.h>
#include <cuda_bf16.h>

// Problem constants
#define BB 32
#define CC 64
#define TT 4096
#define NVEC ((BB * CC * TT) / 4)   // 2,097,152 float4 vectors
#define TVEC (TT / 4)               // 1024 (power of two)

#define GRID 1024
#define BLOCK 256
#define NWARPS (BLOCK / 32)
#define ITERS (NVEC / (GRID * BLOCK))   // exactly 8
#define CHUNK 2                          // float4-pairs per load batch (4 LDG.128)

__device__ float g_partials[GRID];
__device__ unsigned int g_done_count = 0;   // self-resetting per launch

__device__ __forceinline__ float block_reduce(float x)
{
    __shared__ float swarp[NWARPS];
    #pragma unroll
    for (int off = 16; off > 0; off >>= 1)
        x += __shfl_down_sync(0xFFFFFFFFu, x, off);
    int lane = threadIdx.x & 31;
    int wid  = threadIdx.x >> 5;
    if (lane == 0) swarp[wid] = x;
    __syncthreads();
    if (wid == 0) {
        x = (lane < NWARPS) ? swarp[lane] : 0.0f;
        #pragma unroll
        for (int off = NWARPS / 2; off > 0; off >>= 1)
            x += __shfl_down_sync(0xFFFFFFFFu, x, off);
    }
    return x;  // valid in thread 0
}

// Champion (R7): regs pinned to 32 via minBlocks=8 -> 8 CTAs/SM, occ ~84%,
// 4 LDG.128 front-batched per chunk (MLP=4). Block-level aggregation tree
// keeps global-atomic contention at 1024 ops (R15 showed 8192 single-address
// atomics + fences cost ~6us). Memory phase runs at the path-independent
// LTS cap; launch overhead ~1.9us is the irreducible remainder.
__global__ __launch_bounds__(BLOCK, 8) void wass_fused_kernel(
    const float4* __restrict__ yp, const float4* __restrict__ yt,
    float* __restrict__ out)
{
    const int v0 = blockIdx.x * BLOCK + threadIdx.x;
    const int S  = GRID * BLOCK;

    float acc = 0.0f;

    #pragma unroll
    for (int c = 0; c < ITERS / CHUNK; c++) {
        const int va = v0 + (2 * c + 0) * S;
        const int vb = v0 + (2 * c + 1) * S;

        // 4 loads front-batched before any compute.
        float4 p0 = yp[va];
        float4 t0 = yt[va];
        float4 p1 = yp[vb];
        float4 t1 = yt[vb];

        float w0 = (float)(TT - 4 * (va & (TVEC - 1)));
        float w1 = (float)(TT - 4 * (vb & (TVEC - 1)));

        acc += fabsf(p0.x - t0.x) * w0 + fabsf(p0.y - t0.y) * (w0 - 1.0f)
             + fabsf(p0.z - t0.z) * (w0 - 2.0f) + fabsf(p0.w - t0.w) * (w0 - 3.0f);
        acc += fabsf(p1.x - t1.x) * w1 + fabsf(p1.y - t1.y) * (w1 - 1.0f)
             + fabsf(p1.z - t1.z) * (w1 - 2.0f) + fabsf(p1.w - t1.w) * (w1 - 3.0f);
    }

    float bsum = block_reduce(acc);

    __shared__ bool s_is_last;
    if (threadIdx.x == 0) {
        g_partials[blockIdx.x] = bsum;
        __threadfence();                       // partial visible before counting
        unsigned int n = atomicAdd(&g_done_count, 1u);
        s_is_last = (n == GRID - 1);
        if (s_is_last) g_done_count = 0;       // reset for next graph replay
    }
    __syncthreads();

    if (s_is_last) {
        // Deterministic final reduce: fixed order over g_partials.
        float a = 0.0f;
        #pragma unroll 4
        for (int i = threadIdx.x; i < GRID; i += BLOCK)
            a += g_partials[i];
        float total = block_reduce(a);
        if (threadIdx.x == 0) {
            double scaling = 2.0 / ((double)TT * (double)CC * (double)(TT + 1));
            out[0] = (float)((double)total * scaling / (double)BB);
        }
    }
}

extern "C" void kernel_launch(void* const* d_in, const int* in_sizes, int n_in,
                              void* d_out, int out_size)
{
    const float4* yp = reinterpret_cast<const float4*>(d_in[0]);
    const float4* yt = reinterpret_cast<const float4*>(d_in[1]);
    float* out = reinterpret_cast<float*>(d_out);
    wass_fused_kernel<<<GRID, BLOCK>>>(yp, yt, out);
}